// round 8
// baseline (speedup 1.0000x reference)
#include <cuda_runtime.h>
#include <cuda_bf16.h>
#include <cstdint>

#define N_GRAPHS 4096

// ---------------------------------------------------------------------------
// Single fused kernel. Each block folds the weights itself (6KB working set,
// L1-resident after first block per SM) — no separate prep launch.
//
// B-fragment layout in smem (mma.m16n8k16 B lane layout, reg-paired for
// 64-bit LDS):  index = (((v*8 + nt)*32) + lane)*2 + r
//   v: 0 = bf16 hi part, 1 = bf16 lo residual
//   nt: n-tile 0..7 (cols 8nt..8nt+7 of combined W[16 x 64])
//   r: fragment register 0..1 (k rows +0 / +8)
//   lane: b(r) packs W[2*(lane%4)+8r][8nt+lane/4] (lo half) and
//                 W[2*(lane%4)+8r+1][...] (hi half)
// Combined W cols: n<32 -> 0.5*(W_z[0,0]+W_z[1,0])[k][n]  (z path, prescaled)
//                  n>=32 ->     (W_h[0,0]+W_h[1,0])[k][n-32] (t path)
// bz prescaled by 0.5 (z' = z/2 so 1-sigmoid(z) = 0.5 - 0.5*tanh(z')).
// ---------------------------------------------------------------------------

__device__ __forceinline__ uint32_t smem_u32(const void* p) {
    uint32_t a;
    asm("{ .reg .u64 t; cvta.to.shared.u64 t, %1; cvt.u32.u64 %0, t; }" : "=r"(a) : "l"(p));
    return a;
}
__device__ __forceinline__ float tanh_fast(float v) {
    float r; asm("tanh.approx.f32 %0, %1;" : "=f"(r) : "f"(v)); return r;
}
__device__ __forceinline__ uint32_t cvt_bf16x2(float lo, float hi) {
    uint32_t r;  // packs: low half = lo, high half = hi
    asm("cvt.rn.bf16x2.f32 %0, %1, %2;" : "=r"(r) : "f"(hi), "f"(lo));
    return r;
}
__device__ __forceinline__ void mma_bf16(float* d, const uint32_t* a, uint32_t b0, uint32_t b1) {
    asm volatile(
        "mma.sync.aligned.m16n8k16.row.col.f32.bf16.bf16.f32 "
        "{%0,%1,%2,%3}, {%4,%5,%6,%7}, {%8,%9}, {%0,%1,%2,%3};"
        : "+f"(d[0]), "+f"(d[1]), "+f"(d[2]), "+f"(d[3])
        : "r"(a[0]), "r"(a[1]), "r"(a[2]), "r"(a[3]), "r"(b0), "r"(b1));
}
__device__ __forceinline__ uint2 lds_v2(uint32_t addr) {
    uint2 v;
    asm volatile("ld.shared.v2.b32 {%0, %1}, [%2];" : "=r"(v.x), "=r"(v.y) : "r"(addr));
    return v;
}

// ---------------------------------------------------------------------------
// SMEM: 0: Bfrag(4096)  4096: bz(128)  4224: bh(128)  4352: wl(128)
//       4480: wsum(64)   total 4544
// ---------------------------------------------------------------------------
#define OFF_BZ  4096
#define OFF_BH  4224
#define OFF_WL  4352
#define OFF_WS  4480
#define SMEM_SZ 4544

__global__ __launch_bounds__(512, 2)
void rgcn_kernel(const float* __restrict__ x,
                 const float* __restrict__ Wz, const float* __restrict__ bz,
                 const float* __restrict__ Wh, const float* __restrict__ bh,
                 const float* __restrict__ wl, const float* __restrict__ bl,
                 float* __restrict__ out) {
    extern __shared__ char smem[];
    const uint32_t sb = smem_u32(smem);
    const int t    = threadIdx.x;
    const int lane = t & 31;
    const int wid  = t >> 5;

    // ---- A-fragment LDG first (latency overlap with the weight fold) ----
    // warp wid covers 16 nodes: rows mbase..mbase+15 of x.
    const int gr  = lane >> 2;
    const int gc2 = lane & 3;                       // float2 col (cols 2gc2, 2gc2+1)
    const int mbase = (blockIdx.x << 8) + (wid << 4);
    const float2* xf = reinterpret_cast<const float2*>(x);
    const size_t r0 = (size_t)(mbase + gr) << 3;    // row * 8 float2s
    float2 fA = xf[r0 + gc2];
    float2 fB = xf[r0 + gc2 + 4];
    float2 fC = xf[r0 + 64 + gc2];                  // row +8
    float2 fD = xf[r0 + 64 + gc2 + 4];

    // ---- in-block weight fold: 1024 B-fragment words, 2 per thread ----
#pragma unroll
    for (int rep = 0; rep < 2; rep++) {
        int i  = t + (rep << 9);
        int r  = i & 1;
        int l  = (i >> 1) & 31;
        int nt = (i >> 6) & 7;
        int v  = i >> 9;
        int n  = nt * 8 + (l >> 2);
        int k  = ((l & 3) << 1) + (r << 3);
        float w0, w1;
        if (n < 32) {                     // W shape (2,1,48,32); rows k<16 = x part
            w0 = 0.5f * (Wz[k * 32 + n] + Wz[1536 + k * 32 + n]);
            w1 = 0.5f * (Wz[(k + 1) * 32 + n] + Wz[1536 + (k + 1) * 32 + n]);
        } else {
            int nn = n - 32;
            w0 = Wh[k * 32 + nn] + Wh[1536 + k * 32 + nn];
            w1 = Wh[(k + 1) * 32 + nn] + Wh[1536 + (k + 1) * 32 + nn];
        }
        if (v == 1) {                     // lo residual
            w0 -= __bfloat162float(__float2bfloat16(w0));
            w1 -= __bfloat162float(__float2bfloat16(w1));
        }
        reinterpret_cast<uint32_t*>(smem)[i] = cvt_bf16x2(w0, w1);
    }
    if (t < 32) {
        reinterpret_cast<float*>(smem + OFF_BZ)[t] = 0.5f * bz[t];
        reinterpret_cast<float*>(smem + OFF_BH)[t] = bh[t];
        reinterpret_cast<float*>(smem + OFF_WL)[t] = wl[t];
    }

    // ---- bf16 hi/lo split of A fragments (residual in owning lane) ----
    uint32_t Ah[4], Al[4];
    {
        uint32_t h;
        h = cvt_bf16x2(fA.x, fA.y); Ah[0] = h;
        Al[0] = cvt_bf16x2(fA.x - __uint_as_float(h << 16),
                           fA.y - __uint_as_float(h & 0xffff0000u));
        h = cvt_bf16x2(fC.x, fC.y); Ah[1] = h;
        Al[1] = cvt_bf16x2(fC.x - __uint_as_float(h << 16),
                           fC.y - __uint_as_float(h & 0xffff0000u));
        h = cvt_bf16x2(fB.x, fB.y); Ah[2] = h;
        Al[2] = cvt_bf16x2(fB.x - __uint_as_float(h << 16),
                           fB.y - __uint_as_float(h & 0xffff0000u));
        h = cvt_bf16x2(fD.x, fD.y); Ah[3] = h;
        Al[3] = cvt_bf16x2(fD.x - __uint_as_float(h << 16),
                           fD.y - __uint_as_float(h & 0xffff0000u));
    }
    __syncthreads();

    const float* sbz = reinterpret_cast<const float*>(smem + OFF_BZ);
    const float* sbh = reinterpret_cast<const float*>(smem + OFF_BH);
    const float* swl = reinterpret_cast<const float*>(smem + OFF_WL);
    const uint32_t bfb = sb + lane * 8;             // per-lane B-frag base
    const int c0 = gc2 << 1;

    float s = 0.f;
#pragma unroll
    for (int p = 0; p < 4; p++) {
        // B fragments: (v,nt) at offset ((v*8+nt)*32)*8 from per-lane base
        uint2 Bzh = lds_v2(bfb + (p)      * 256);
        uint2 Bth = lds_v2(bfb + (p + 4)  * 256);
        uint2 Bzl = lds_v2(bfb + (p + 8)  * 256);
        uint2 Btl = lds_v2(bfb + (p + 12) * 256);
        float2 bz2 = *reinterpret_cast<const float2*>(sbz + 8 * p + c0);
        float2 bh2 = *reinterpret_cast<const float2*>(sbh + 8 * p + c0);
        float2 wl2 = *reinterpret_cast<const float2*>(swl + 8 * p + c0);

        float Dz[4] = {0.f, 0.f, 0.f, 0.f};
        float Dt[4] = {0.f, 0.f, 0.f, 0.f};
        mma_bf16(Dz, Ah, Bzh.x, Bzh.y);
        mma_bf16(Dt, Ah, Bth.x, Bth.y);
        mma_bf16(Dz, Al, Bzh.x, Bzh.y);
        mma_bf16(Dt, Al, Bth.x, Bth.y);
        mma_bf16(Dz, Ah, Bzl.x, Bzl.y);
        mma_bf16(Dt, Ah, Btl.x, Btl.y);

#pragma unroll
        for (int i = 0; i < 4; i++) {
            float zb = (i & 1) ? bz2.y : bz2.x;
            float hb = (i & 1) ? bh2.y : bh2.x;
            float wv = (i & 1) ? wl2.y : wl2.x;
            float z  = Dz[i] + zb;                       // already pre-halved
            float tt = Dt[i] + hb;
            float e = fmaf(-0.5f, tanh_fast(z), 0.5f);   // 1 - sigmoid
            float h = tanh_fast(tt);
            s = fmaf(fmaxf(e * h, 0.f), wv, s);
        }
    }

    // ---- block reduction over the graph's 256 nodes (16 warps) ----
#pragma unroll
    for (int off = 16; off > 0; off >>= 1)
        s += __shfl_xor_sync(0xffffffffu, s, off);
    float* wsum = reinterpret_cast<float*>(smem + OFF_WS);
    if (lane == 0) wsum[wid] = s;
    __syncthreads();
    if (wid == 0) {
        float v = (lane < 16) ? wsum[lane] : 0.f;
#pragma unroll
        for (int off = 8; off > 0; off >>= 1)
            v += __shfl_xor_sync(0xffffffffu, v, off);
        if (lane == 0)
            out[blockIdx.x] = v * (1.0f / 256.0f) + bl[0];
    }
}

// ---------------------------------------------------------------------------
// Inputs: 0:x 1:edge_index 2:edge_weight 3:batch 4:W_z 5:b_z 6:W_r 7:b_r
//         8:W_h 9:b_h 10:W_lin 11:b_lin
// edge_index/edge_weight/batch/W_r/b_r mathematically unused (K=1, h0=0,
// batch = repeat(arange(4096),256)).
// ---------------------------------------------------------------------------
extern "C" void kernel_launch(void* const* d_in, const int* in_sizes, int n_in,
                              void* d_out, int out_size) {
    (void)in_sizes; (void)n_in; (void)out_size;
    const float* x  = (const float*)d_in[0];
    const float* Wz = (const float*)d_in[4];
    const float* bz = (const float*)d_in[5];
    const float* Wh = (const float*)d_in[8];
    const float* bh = (const float*)d_in[9];
    const float* wl = (const float*)d_in[10];
    const float* bl = (const float*)d_in[11];
    float* out = (float*)d_out;

    rgcn_kernel<<<N_GRAPHS, 512, SMEM_SZ>>>(x, Wz, bz, Wh, bh, wl, bl, out);
}

// round 9
// speedup vs baseline: 1.2880x; 1.2880x over previous
#include <cuda_runtime.h>
#include <cuda_bf16.h>
#include <cstdint>

#define N_GRAPHS 4096

// ---------------------------------------------------------------------------
// g_Bfrag: folded weights in mma.m16n8k16 B-fragment lane layout, regs paired
// for 64-bit loads:  index = (((v*8 + nt)*32) + lane)*2 + r
//   v: 0 = bf16 hi part, 1 = bf16 lo residual
//   nt: n-tile 0..7 (cols 8nt..8nt+7 of combined W[16 x 64])
//   r: fragment register 0..1 (k rows +0 / +8)
//   lane: b(r) packs W[2*(lane%4)+8r][8nt+lane/4] (lo half) and
//                 W[2*(lane%4)+8r+1][...] (hi half)
// Combined W cols: n<32 -> 0.5*(W_z[0,0]+W_z[1,0])[k][n]  (z path, prescaled)
//                  n>=32 ->     (W_h[0,0]+W_h[1,0])[k][n-32] (t path)
// g_bz prescaled by 0.5 (z' = z/2 so 1-sigmoid(z) = 0.5 - 0.5*tanh(z')).
// Folded ONCE here — R8 showed per-block folding floods L1TEX.
// ---------------------------------------------------------------------------
__device__ uint32_t g_Bfrag[1024];
__device__ float g_bz[32];
__device__ float g_bh[32];
__device__ float g_wl[32];
__device__ float g_bl;

__device__ __forceinline__ uint32_t cvt_bf16x2(float lo, float hi) {
    uint32_t r;  // packs: low half = lo, high half = hi
    asm("cvt.rn.bf16x2.f32 %0, %1, %2;" : "=r"(r) : "f"(hi), "f"(lo));
    return r;
}

__global__ void prep_kernel(const float* __restrict__ Wz, const float* __restrict__ bz,
                            const float* __restrict__ Wh, const float* __restrict__ bh,
                            const float* __restrict__ wl, const float* __restrict__ bl) {
    int i = threadIdx.x;                   // 1024 threads
    int r  = i & 1;
    int l  = (i >> 1) & 31;
    int nt = (i >> 6) & 7;
    int v  = i >> 9;
    int n  = nt * 8 + (l >> 2);
    int k  = ((l & 3) << 1) + (r << 3);
    float w0, w1;
    if (n < 32) {                          // W shape (2,1,48,32); rows k<16 = x part
        w0 = 0.5f * (Wz[k * 32 + n] + Wz[1536 + k * 32 + n]);
        w1 = 0.5f * (Wz[(k + 1) * 32 + n] + Wz[1536 + (k + 1) * 32 + n]);
    } else {
        int nn = n - 32;
        w0 = Wh[k * 32 + nn] + Wh[1536 + k * 32 + nn];
        w1 = Wh[(k + 1) * 32 + nn] + Wh[1536 + (k + 1) * 32 + nn];
    }
    if (v == 1) {                          // lo residual
        w0 -= __bfloat162float(__float2bfloat16(w0));
        w1 -= __bfloat162float(__float2bfloat16(w1));
    }
    g_Bfrag[i] = cvt_bf16x2(w0, w1);
    if (i < 32) { g_bz[i] = 0.5f * bz[i]; g_bh[i] = bh[i]; g_wl[i] = wl[i]; }
    if (i == 0) g_bl = bl[0];
}

// ---------------------------------------------------------------------------
// Baseline-ISA helpers (compile for plain sm_103 — no arch-accelerated feats)
// ---------------------------------------------------------------------------
__device__ __forceinline__ uint32_t smem_u32(const void* p) {
    uint32_t a;
    asm("{ .reg .u64 t; cvta.to.shared.u64 t, %1; cvt.u32.u64 %0, t; }" : "=r"(a) : "l"(p));
    return a;
}
__device__ __forceinline__ float tanh_fast(float v) {
    float r; asm("tanh.approx.f32 %0, %1;" : "=f"(r) : "f"(v)); return r;
}
__device__ __forceinline__ void mma_bf16(float* d, const uint32_t* a, uint32_t b0, uint32_t b1) {
    asm volatile(
        "mma.sync.aligned.m16n8k16.row.col.f32.bf16.bf16.f32 "
        "{%0,%1,%2,%3}, {%4,%5,%6,%7}, {%8,%9}, {%0,%1,%2,%3};"
        : "+f"(d[0]), "+f"(d[1]), "+f"(d[2]), "+f"(d[3])
        : "r"(a[0]), "r"(a[1]), "r"(a[2]), "r"(a[3]), "r"(b0), "r"(b1));
}
__device__ __forceinline__ uint2 lds_v2(uint32_t addr) {
    uint2 v;
    asm volatile("ld.shared.v2.b32 {%0, %1}, [%2];" : "=r"(v.x), "=r"(v.y) : "r"(addr));
    return v;
}

// ---------------------------------------------------------------------------
// SMEM: 0: Bfrag(4096)  4096: bz(128)  4224: bh(128)  4352: wl(128)
//       4480: wsum(64)   total 4544
// ---------------------------------------------------------------------------
#define OFF_BZ  4096
#define OFF_BH  4224
#define OFF_WL  4352
#define OFF_WS  4480
#define SMEM_SZ 4544

// 512 threads = 16 warps; warp owns ONE m16 tile (16 nodes); block = 1 graph.
// R8 shape (regs ~60, occ 45%) WITHOUT the per-block weight fold.
__global__ __launch_bounds__(512, 2)
void rgcn_kernel(const float* __restrict__ x, float* __restrict__ out) {
    extern __shared__ char smem[];
    const uint32_t sb = smem_u32(smem);
    const int t    = threadIdx.x;
    const int lane = t & 31;
    const int wid  = t >> 5;

    // ---- A-fragment LDG first (latency overlap with staging) ----
    // A frag (row.col m16n8k16): a0 = x[R+gr][2gc2,2gc2+1], a1 = row +8,
    // a2/a3 = cols +8.  R = block*256 + wid*16.
    const int gr  = lane >> 2;
    const int gc2 = lane & 3;
    const int mbase = (blockIdx.x << 8) + (wid << 4);
    const float2* xf = reinterpret_cast<const float2*>(x);
    const size_t r0 = (size_t)(mbase + gr) << 3;    // row * 8 float2s
    float2 fA = xf[r0 + gc2];
    float2 fB = xf[r0 + gc2 + 4];
    float2 fC = xf[r0 + 64 + gc2];                  // row +8
    float2 fD = xf[r0 + 64 + gc2 + 4];

    // ---- stage prefolded B fragments (4KB, one coalesced uint4 round) ----
    if (t < 256)
        reinterpret_cast<uint4*>(smem)[t] = reinterpret_cast<const uint4*>(g_Bfrag)[t];
    else if (t < 288) {
        int i = t - 256;
        reinterpret_cast<float*>(smem + OFF_BZ)[i] = g_bz[i];
        reinterpret_cast<float*>(smem + OFF_BH)[i] = g_bh[i];
        reinterpret_cast<float*>(smem + OFF_WL)[i] = g_wl[i];
    }

    // ---- bf16 hi/lo split of A fragments (residual in owning lane) ----
    uint32_t Ah[4], Al[4];
    {
        uint32_t h;
        h = cvt_bf16x2(fA.x, fA.y); Ah[0] = h;
        Al[0] = cvt_bf16x2(fA.x - __uint_as_float(h << 16),
                           fA.y - __uint_as_float(h & 0xffff0000u));
        h = cvt_bf16x2(fC.x, fC.y); Ah[1] = h;
        Al[1] = cvt_bf16x2(fC.x - __uint_as_float(h << 16),
                           fC.y - __uint_as_float(h & 0xffff0000u));
        h = cvt_bf16x2(fB.x, fB.y); Ah[2] = h;
        Al[2] = cvt_bf16x2(fB.x - __uint_as_float(h << 16),
                           fB.y - __uint_as_float(h & 0xffff0000u));
        h = cvt_bf16x2(fD.x, fD.y); Ah[3] = h;
        Al[3] = cvt_bf16x2(fD.x - __uint_as_float(h << 16),
                           fD.y - __uint_as_float(h & 0xffff0000u));
    }
    __syncthreads();

    const float* sbz = reinterpret_cast<const float*>(smem + OFF_BZ);
    const float* sbh = reinterpret_cast<const float*>(smem + OFF_BH);
    const float* swl = reinterpret_cast<const float*>(smem + OFF_WL);
    const uint32_t bfb = sb + lane * 8;             // per-lane B-frag base
    const int c0 = gc2 << 1;

    float s = 0.f;
#pragma unroll
    for (int p = 0; p < 4; p++) {
        // B fragments: (v,nt) at offset (v*8+nt)*256 from per-lane base
        uint2 Bzh = lds_v2(bfb + (p)      * 256);
        uint2 Bth = lds_v2(bfb + (p + 4)  * 256);
        uint2 Bzl = lds_v2(bfb + (p + 8)  * 256);
        uint2 Btl = lds_v2(bfb + (p + 12) * 256);
        float2 bz2 = *reinterpret_cast<const float2*>(sbz + 8 * p + c0);
        float2 bh2 = *reinterpret_cast<const float2*>(sbh + 8 * p + c0);
        float2 wl2 = *reinterpret_cast<const float2*>(swl + 8 * p + c0);

        float Dz[4] = {0.f, 0.f, 0.f, 0.f};
        float Dt[4] = {0.f, 0.f, 0.f, 0.f};
        mma_bf16(Dz, Ah, Bzh.x, Bzh.y);
        mma_bf16(Dt, Ah, Bth.x, Bth.y);
        mma_bf16(Dz, Al, Bzh.x, Bzh.y);
        mma_bf16(Dt, Al, Bth.x, Bth.y);
        mma_bf16(Dz, Ah, Bzl.x, Bzl.y);
        mma_bf16(Dt, Ah, Btl.x, Btl.y);

#pragma unroll
        for (int i = 0; i < 4; i++) {
            float zb = (i & 1) ? bz2.y : bz2.x;
            float hb = (i & 1) ? bh2.y : bh2.x;
            float wv = (i & 1) ? wl2.y : wl2.x;
            float z  = Dz[i] + zb;                       // already pre-halved
            float tt = Dt[i] + hb;
            float e = fmaf(-0.5f, tanh_fast(z), 0.5f);   // 1 - sigmoid
            float h = tanh_fast(tt);
            s = fmaf(fmaxf(e * h, 0.f), wv, s);
        }
    }

    // ---- block reduction over the graph's 256 nodes (16 warps) ----
#pragma unroll
    for (int off = 16; off > 0; off >>= 1)
        s += __shfl_xor_sync(0xffffffffu, s, off);
    float* wsum = reinterpret_cast<float*>(smem + OFF_WS);
    if (lane == 0) wsum[wid] = s;
    __syncthreads();
    if (wid == 0) {
        float v = (lane < 16) ? wsum[lane] : 0.f;
#pragma unroll
        for (int off = 8; off > 0; off >>= 1)
            v += __shfl_xor_sync(0xffffffffu, v, off);
        if (lane == 0)
            out[blockIdx.x] = v * (1.0f / 256.0f) + g_bl;
    }
}

// ---------------------------------------------------------------------------
// Inputs: 0:x 1:edge_index 2:edge_weight 3:batch 4:W_z 5:b_z 6:W_r 7:b_r
//         8:W_h 9:b_h 10:W_lin 11:b_lin
// edge_index/edge_weight/batch/W_r/b_r mathematically unused (K=1, h0=0,
// batch = repeat(arange(4096),256)).
// ---------------------------------------------------------------------------
extern "C" void kernel_launch(void* const* d_in, const int* in_sizes, int n_in,
                              void* d_out, int out_size) {
    (void)in_sizes; (void)n_in; (void)out_size;
    const float* x  = (const float*)d_in[0];
    const float* Wz = (const float*)d_in[4];
    const float* bz = (const float*)d_in[5];
    const float* Wh = (const float*)d_in[8];
    const float* bh = (const float*)d_in[9];
    const float* wl = (const float*)d_in[10];
    const float* bl = (const float*)d_in[11];
    float* out = (float*)d_out;

    prep_kernel<<<1, 1024>>>(Wz, bz, Wh, bh, wl, bl);
    rgcn_kernel<<<N_GRAPHS, 512, SMEM_SZ>>>(x, out);
}

// round 10
// speedup vs baseline: 1.5953x; 1.2386x over previous
#include <cuda_runtime.h>
#include <cuda_bf16.h>
#include <cstdint>

#define N_GRAPHS 4096

// ---------------------------------------------------------------------------
// Fully fused single kernel (no prep launch).
// Weight fold is done per-block but with COALESCED global loads staged through
// smem (R8's regression came from scattered per-block LDGs).
//
// B-fragment layout in smem (mma.m16n8k16 B lane layout, reg-paired for
// 64-bit LDS): index = (((v*8 + nt)*32) + lane)*2 + r
//   v: 0 = bf16 hi part of W, 1 = bf16 lo residual of W
//   nt: n-tile 0..7 (cols 8nt..8nt+7 of combined W[16 x 64])
//   r: fragment register 0..1 (k rows +0 / +8)
// Combined W cols: n<32 -> 0.5*(W_z[0,0]+W_z[1,0])[k][n]  (z path, prescaled)
//                  n>=32 ->     (W_h[0,0]+W_h[1,0])[k][n-32] (t path)
// bz prescaled by 0.5 (z' = z/2 so 1-sigmoid(z) = 0.5 - 0.5*tanh(z')).
//
// Precision: W is 2-term bf16 (hi+lo), x is 1-term bf16 (hi only).
// Dropped term xl@W is zero-mean per node and averages out in the 256-node
// graph mean -> expected rel_err ~1e-4 (gate is 1e-3).
// ---------------------------------------------------------------------------

__device__ __forceinline__ uint32_t smem_u32(const void* p) {
    uint32_t a;
    asm("{ .reg .u64 t; cvta.to.shared.u64 t, %1; cvt.u32.u64 %0, t; }" : "=r"(a) : "l"(p));
    return a;
}
__device__ __forceinline__ float tanh_fast(float v) {
    float r; asm("tanh.approx.f32 %0, %1;" : "=f"(r) : "f"(v)); return r;
}
__device__ __forceinline__ uint32_t cvt_bf16x2(float lo, float hi) {
    uint32_t r;  // packs: low half = lo, high half = hi
    asm("cvt.rn.bf16x2.f32 %0, %1, %2;" : "=r"(r) : "f"(hi), "f"(lo));
    return r;
}
__device__ __forceinline__ void mma_bf16(float* d, const uint32_t* a, uint32_t b0, uint32_t b1) {
    asm volatile(
        "mma.sync.aligned.m16n8k16.row.col.f32.bf16.bf16.f32 "
        "{%0,%1,%2,%3}, {%4,%5,%6,%7}, {%8,%9}, {%0,%1,%2,%3};"
        : "+f"(d[0]), "+f"(d[1]), "+f"(d[2]), "+f"(d[3])
        : "r"(a[0]), "r"(a[1]), "r"(a[2]), "r"(a[3]), "r"(b0), "r"(b1));
}
__device__ __forceinline__ uint2 lds_v2(uint32_t addr) {
    uint2 v;
    asm volatile("ld.shared.v2.b32 {%0, %1}, [%2];" : "=r"(v.x), "=r"(v.y) : "r"(addr));
    return v;
}

// ---------------------------------------------------------------------------
// SMEM: 0: Bfrag(4096)  4096: sZ(2048)  6144: sT(2048)
//       8192: bz(128)  8320: bh(128)  8448: wl(128)  8576: wsum(32)
// ---------------------------------------------------------------------------
#define OFF_SZ  4096
#define OFF_ST  6144
#define OFF_BZ  8192
#define OFF_BH  8320
#define OFF_WL  8448
#define OFF_WS  8576
#define SMEM_SZ 8608

// 256 threads = 8 warps; warp owns TWO m16 tiles (32 nodes); block = 1 graph.
__global__ __launch_bounds__(256, 4)
void rgcn_kernel(const float* __restrict__ x,
                 const float* __restrict__ Wz, const float* __restrict__ bz,
                 const float* __restrict__ Wh, const float* __restrict__ bh,
                 const float* __restrict__ wl, const float* __restrict__ bl,
                 float* __restrict__ out) {
    extern __shared__ char smem[];
    const uint32_t sb = smem_u32(smem);
    const int t    = threadIdx.x;
    const int lane = t & 31;
    const int wid  = t >> 5;

    // ---- A-fragment LDG first (latency overlap with weight fold) ----
    const int gr  = lane >> 2;
    const int gc2 = lane & 3;
    const int mbase = (blockIdx.x << 8) + (wid << 5);
    const float2* xf = reinterpret_cast<const float2*>(x);
    float2 f[2][4];
#pragma unroll
    for (int m = 0; m < 2; m++) {
        const size_t r0 = (size_t)(mbase + (m << 4) + gr) << 3;   // row*8 float2s
        f[m][0] = xf[r0 + gc2];
        f[m][1] = xf[r0 + 64 + gc2];       // row +8
        f[m][2] = xf[r0 + gc2 + 4];        // cols +8
        f[m][3] = xf[r0 + 64 + gc2 + 4];
    }

    // ---- stage summed weight slices COALESCED into smem ----
    float* sZ = reinterpret_cast<float*>(smem + OFF_SZ);
    float* sT = reinterpret_cast<float*>(smem + OFF_ST);
#pragma unroll
    for (int rep = 0; rep < 2; rep++) {
        int j = t + (rep << 8);            // 0..511  (W shape (2,1,48,32))
        sZ[j] = Wz[j] + Wz[1536 + j];
        sT[j] = Wh[j] + Wh[1536 + j];
    }
    if (t < 32) {
        reinterpret_cast<float*>(smem + OFF_BZ)[t] = 0.5f * bz[t];
        reinterpret_cast<float*>(smem + OFF_BH)[t] = bh[t];
        reinterpret_cast<float*>(smem + OFF_WL)[t] = wl[t];
    }
    __syncthreads();

    // ---- fold B fragments from smem (4 words/thread, small LDS gather) ----
    uint32_t* bf = reinterpret_cast<uint32_t*>(smem);
#pragma unroll
    for (int rep = 0; rep < 4; rep++) {
        int i  = t + (rep << 8);
        int r  = i & 1;
        int l  = (i >> 1) & 31;
        int nt = (i >> 6) & 7;
        int v  = i >> 9;
        int n  = nt * 8 + (l >> 2);
        int k  = ((l & 3) << 1) + (r << 3);
        const float* base = (n < 32) ? sZ : sT;
        float sc = (n < 32) ? 0.5f : 1.0f;
        int nn = n & 31;
        float w0 = sc * base[k * 32 + nn];
        float w1 = sc * base[(k + 1) * 32 + nn];
        if (v == 1) {                      // lo residual of W
            w0 -= __bfloat162float(__float2bfloat16(w0));
            w1 -= __bfloat162float(__float2bfloat16(w1));
        }
        bf[i] = cvt_bf16x2(w0, w1);
    }

    // ---- bf16 A fragments (hi only; xl term dropped by design) ----
    uint32_t Ah[2][4];
#pragma unroll
    for (int m = 0; m < 2; m++) {
#pragma unroll
        for (int q = 0; q < 4; q++)
            Ah[m][q] = cvt_bf16x2(f[m][q].x, f[m][q].y);
    }
    __syncthreads();

    const float* sbz = reinterpret_cast<const float*>(smem + OFF_BZ);
    const float* sbh = reinterpret_cast<const float*>(smem + OFF_BH);
    const float* swl = reinterpret_cast<const float*>(smem + OFF_WL);
    const uint32_t bfb = sb + lane * 8;             // per-lane B-frag base
    const int c0 = gc2 << 1;

    float s = 0.f;
#pragma unroll
    for (int p = 0; p < 4; p++) {
        // B fragments: (v,nt) at offset (v*8+nt)*256 from per-lane base
        uint2 Bzh = lds_v2(bfb + (p)      * 256);
        uint2 Bth = lds_v2(bfb + (p + 4)  * 256);
        uint2 Bzl = lds_v2(bfb + (p + 8)  * 256);
        uint2 Btl = lds_v2(bfb + (p + 12) * 256);
        float2 bz2 = *reinterpret_cast<const float2*>(sbz + 8 * p + c0);
        float2 bh2 = *reinterpret_cast<const float2*>(sbh + 8 * p + c0);
        float2 wl2 = *reinterpret_cast<const float2*>(swl + 8 * p + c0);

#pragma unroll
        for (int m = 0; m < 2; m++) {
            float Dz[4] = {0.f, 0.f, 0.f, 0.f};
            float Dt[4] = {0.f, 0.f, 0.f, 0.f};
            mma_bf16(Dz, Ah[m], Bzh.x, Bzh.y);
            mma_bf16(Dt, Ah[m], Bth.x, Bth.y);
            mma_bf16(Dz, Ah[m], Bzl.x, Bzl.y);
            mma_bf16(Dt, Ah[m], Btl.x, Btl.y);

#pragma unroll
            for (int i = 0; i < 4; i++) {
                float zb = (i & 1) ? bz2.y : bz2.x;
                float hb = (i & 1) ? bh2.y : bh2.x;
                float wv = (i & 1) ? wl2.y : wl2.x;
                float z  = Dz[i] + zb;                       // already pre-halved
                float tt = Dt[i] + hb;
                float e = fmaf(-0.5f, tanh_fast(z), 0.5f);   // 1 - sigmoid
                float h = tanh_fast(tt);
                s = fmaf(fmaxf(e * h, 0.f), wv, s);
            }
        }
    }

    // ---- block reduction over the graph's 256 nodes (8 warps) ----
#pragma unroll
    for (int off = 16; off > 0; off >>= 1)
        s += __shfl_xor_sync(0xffffffffu, s, off);
    float* wsum = reinterpret_cast<float*>(smem + OFF_WS);
    if (lane == 0) wsum[wid] = s;
    __syncthreads();
    if (t == 0) {
        float tot = ((wsum[0] + wsum[1]) + (wsum[2] + wsum[3])) +
                    ((wsum[4] + wsum[5]) + (wsum[6] + wsum[7]));
        out[blockIdx.x] = tot * (1.0f / 256.0f) + bl[0];
    }
}

// ---------------------------------------------------------------------------
// Inputs: 0:x 1:edge_index 2:edge_weight 3:batch 4:W_z 5:b_z 6:W_r 7:b_r
//         8:W_h 9:b_h 10:W_lin 11:b_lin
// edge_index/edge_weight/batch/W_r/b_r mathematically unused (K=1, h0=0,
// batch = repeat(arange(4096),256)).
// ---------------------------------------------------------------------------
extern "C" void kernel_launch(void* const* d_in, const int* in_sizes, int n_in,
                              void* d_out, int out_size) {
    (void)in_sizes; (void)n_in; (void)out_size;
    const float* x  = (const float*)d_in[0];
    const float* Wz = (const float*)d_in[4];
    const float* bz = (const float*)d_in[5];
    const float* Wh = (const float*)d_in[8];
    const float* bh = (const float*)d_in[9];
    const float* wl = (const float*)d_in[10];
    const float* bl = (const float*)d_in[11];
    float* out = (float*)d_out;

    rgcn_kernel<<<N_GRAPHS, 256, SMEM_SZ>>>(x, Wz, bz, Wh, bh, wl, bl, out);
}